// round 2
// baseline (speedup 1.0000x reference)
#include <cuda_runtime.h>
#include <math.h>

// Problem constants (fixed by the reference)
#define N_K        16
#define C_CAT      136          // 16*17/2 upper-tri pairs
#define DIM        64
#define NROWS      8192         // 512 * 16
#define ROWS_PER_BLK 8
#define MAIN_BLOCKS (NROWS / ROWS_PER_BLK)   // 1024

#define LOG2PI_F   1.8378770664093453f
#define NEG_RSQRT2 (-0.70710678118654752440f)

// ---- device scratch (static globals; no allocation) ----
__device__ float d_partials[MAIN_BLOCKS];
__device__ unsigned int d_counter = 0;

// ---------------------------------------------------------------------------
// Fused kernel: per-block redundant constant precompute + main math +
// last-block-done deterministic finalize.  One launch total.
// ---------------------------------------------------------------------------
__global__ __launch_bounds__(256) void fused_kernel(const float* __restrict__ z,
                                                    const float* __restrict__ pi,
                                                    const float* __restrict__ mu,
                                                    float* __restrict__ out)
{
    __shared__ float mu_s[DIM][N_K];               // 4 KB
    __shared__ float z_s [ROWS_PER_BLK][DIM];      // 2 KB
    __shared__ float g_s [ROWS_PER_BLK][N_K];      // 512 B
    __shared__ float rowres[ROWS_PER_BLK];
    __shared__ float red[256];
    __shared__ float s_max, s_sum;
    __shared__ int   s_is_last;
    // per-category constants (computed redundantly by this block)
    __shared__ float c_recip[C_CAT], c_invsig[C_CAT], c_sq[C_CAT],
                     c_base[C_CAT], c_k1[C_CAT], c_mB2[C_CAT];
    __shared__ int   c_ab[C_CAT];

    const int t = threadIdx.x;

    // ---- stage mu and this block's z rows ----
    for (int i = t; i < DIM * N_K; i += 256)
        (&mu_s[0][0])[i] = mu[i];
    const int row0 = blockIdx.x * ROWS_PER_BLK;
    for (int i = t; i < ROWS_PER_BLK * DIM; i += 256)
        (&z_s[0][0])[i] = z[row0 * DIM + i];

    // ---- softmax(pi): max + sum over the 136 logits ----
    const float piv = (t < C_CAT) ? pi[t] : -INFINITY;
    red[t] = piv; __syncthreads();
    for (int o = 128; o; o >>= 1) { if (t < o) red[t] = fmaxf(red[t], red[t + o]); __syncthreads(); }
    if (t == 0) s_max = red[0];
    __syncthreads();
    const float e = (t < C_CAT) ? __expf(piv - s_max) : 0.f;
    red[t] = e; __syncthreads();
    for (int o = 128; o; o >>= 1) { if (t < o) red[t] += red[t + o]; __syncthreads(); }
    if (t == 0) s_sum = red[0];
    __syncthreads();

    // ---- per-category constants (thread t -> category t) ----
    if (t < C_CAT) {
        float tp = fminf(fmaxf(e / s_sum, 1e-16f), 1.0f);
        float lp = -32.0f * LOG2PI_F + logf(tp);   // -0.5*d*log2pi + log(temp_pi)

        int A = 0, rem = t;
        while (rem >= (N_K - A)) { rem -= (N_K - A); ++A; }
        int B = A + rem;

        float invsig = 0.f, k1 = 0.f, mB2 = 0.f;
        #pragma unroll
        for (int d = 0; d < DIM; ++d) {
            float mb = mu_s[d][B];
            float ma = mu_s[d][A];
            float a  = mb - ma;
            invsig = fmaf(a, a, invsig);
            k1     = fmaf(a, mb, k1);
            mB2    = fmaf(mb, mb, mB2);
        }
        float clip_is = fminf(fmaxf(invsig, 1e-12f), 1e30f);
        float sq = sqrtf(clip_is);
        float c0 = 0.5f * (LOG2PI_F - logf(clip_is));
        int diag = (invsig == 0.0f) ? 1 : 0;

        c_recip [t] = diag ? 0.f : (1.0f / invsig);
        c_invsig[t] = invsig;
        c_sq    [t] = sq;
        c_base  [t] = diag ? lp : (lp + c0);
        c_k1    [t] = k1;
        c_mB2   [t] = mB2;
        c_ab    [t] = A | (B << 8) | (diag << 16);
    }
    __syncthreads();

    // ---- main math: one warp per (b,l) row ----
    const int w = t >> 5;        // warp == row within block
    const int l = t & 31;

    // |z|^2 : each lane sums 2 elements, butterfly reduce
    float p = z_s[w][l] * z_s[w][l] + z_s[w][l + 32] * z_s[w][l + 32];
    #pragma unroll
    for (int o = 16; o; o >>= 1) p += __shfl_xor_sync(0xffffffffu, p, o);
    const float z2 = p;

    // g_k = dot(z_row, mu_k): lane (k,half) does a 32-long partial, fold halves
    {
        const int k = l & 15, h = l >> 4;
        float acc = 0.f;
        #pragma unroll
        for (int d = 0; d < 32; ++d)
            acc = fmaf(z_s[w][h * 32 + d], mu_s[h * 32 + d][k], acc);
        acc += __shfl_xor_sync(0xffffffffu, acc, 16);
        if (h == 0) g_s[w][k] = acc;
    }
    __syncwarp();

    // per-category log_p_zc -> two-pass register-buffered logsumexp
    float vbuf[5];
    int nv = 0;
    float m = -INFINITY;
    for (int c = l; c < C_CAT; c += 32) {
        const int ab = c_ab[c];
        const int A = ab & 255, B = (ab >> 8) & 255;
        const float gA = g_s[w][A];
        const float gB = g_s[w][B];
        const float beta_sq = z2 - 2.0f * gB + c_mB2[c];

        float v;
        if (ab & (1 << 16)) {                         // inv_sig == 0 (diag pair)
            v = c_base[c] - 0.5f * beta_sq;
        } else {
            const float nu   = (c_k1[c] - gB + gA) * c_recip[c];
            const float tq   = fmaf(nu * nu, c_invsig[c], -beta_sq);
            const float sq   = c_sq[c];
            const float eta1 = (1.0f - nu) * sq;
            const float eta2 = -nu * sq;
            float cdfd = 0.5f * (erfcf(eta1 * NEG_RSQRT2) - erfcf(eta2 * NEG_RSQRT2));
            cdfd = fminf(fmaxf(cdfd, 1e-16f), 1e30f);
            v = c_base[c] + 0.5f * tq + __logf(cdfd);
        }
        vbuf[nv++] = v;
        m = fmaxf(m, v);
    }

    // warp max
    #pragma unroll
    for (int o = 16; o; o >>= 1) m = fmaxf(m, __shfl_xor_sync(0xffffffffu, m, o));

    // single exp per category
    float ssum = 0.f;
    #pragma unroll
    for (int i = 0; i < 5; ++i)
        if (i < nv) ssum += __expf(vbuf[i] - m);

    // warp sum
    #pragma unroll
    for (int o = 16; o; o >>= 1) ssum += __shfl_xor_sync(0xffffffffu, ssum, o);

    if (l == 0) rowres[w] = m + logf(ssum);
    __syncthreads();

    // ---- per-block partial + last-block-done finalize ----
    if (t == 0) {
        float s = 0.f;
        #pragma unroll
        for (int r = 0; r < ROWS_PER_BLK; ++r) s += rowres[r];
        d_partials[blockIdx.x] = s;
        __threadfence();
        unsigned int ticket = atomicAdd(&d_counter, 1u);
        s_is_last = (ticket == (unsigned)(gridDim.x - 1));
    }
    __syncthreads();

    if (s_is_last) {
        volatile float* vp = d_partials;
        float s = 0.f;
        for (int i = t; i < MAIN_BLOCKS; i += 256) s += vp[i];
        red[t] = s; __syncthreads();
        for (int o = 128; o; o >>= 1) { if (t < o) red[t] += red[t + o]; __syncthreads(); }
        if (t == 0) {
            out[0] = red[0] * (1.0f / (float)NROWS);
            d_counter = 0;                 // reset for next graph replay
        }
    }
}

// ---------------------------------------------------------------------------
extern "C" void kernel_launch(void* const* d_in, const int* in_sizes, int n_in,
                              void* d_out, int out_size)
{
    (void)in_sizes; (void)n_in; (void)out_size;
    const float* z  = (const float*)d_in[0];
    const float* pi = (const float*)d_in[1];
    const float* mu = (const float*)d_in[2];
    float* out = (float*)d_out;

    fused_kernel<<<MAIN_BLOCKS, 256>>>(z, pi, mu, out);
}